// round 17
// baseline (speedup 1.0000x reference)
#include <cuda_runtime.h>
#include <cuda_fp16.h>
#include <cstdint>
#include <math.h>

// Problem constants
#define Bb   4
#define Tt   2048
#define Cc   2048
#define Hh   32
#define Nn   64
#define BT   (Bb*Tt)          // 8192
#define BIGN (BT*Cc)          // 16,777,216
#define WN   (Cc*Cc)          // 4,194,304

// ---------------- scratch ----------------------------------------------------
__device__ float g_r    [BIGN];
__device__ float g_k    [BIGN];
__device__ float g_v    [BIGN];
__device__ float g_v2   [BIGN];
__device__ float g_decay[BIGN];
__device__ float g_ys   [BIGN];
__device__ float g_hpre [BT*160];

// fp16 hi/lo planes (A operands): [0..n) hi, [n..2n) lo
__device__ __half g_pxxx[2*BIGN];
__device__ __half g_pxr [2*BIGN];
__device__ __half g_pxk [2*BIGN];
__device__ __half g_pxv [2*BIGN];
__device__ __half g_pxw [2*BIGN];
__device__ __half g_pxv2[2*BIGN];
__device__ __half g_pyn [2*BIGN];
__device__ __half g_ptw [2*BT*64];   // tanh(xw@dec_w1) hi/lo
__device__ __half g_ptv [2*BT*64];   // tanh(xv2@v2_w1) hi/lo
// fp16 weight planes (B operands, hi only)
__device__ __half g_pWr[WN];
__device__ __half g_pWk[WN];
__device__ __half g_pWv[WN];
__device__ __half g_pWo[WN];
__device__ __half g_pW1[Cc*160];
__device__ __half g_pWd[Cc*64];
__device__ __half g_pWe[Cc*64];
__device__ __half g_pWd2[64*Cc];
__device__ __half g_pWe2[64*Cc];

__device__ __forceinline__ void split2h(float f, __half& h, __half& l) {
    h = __float2half_rn(f);
    l = __float2half_rn(f - __half2float(h));
}

// ---------------- E1: token shift -> xxx planes -----------------------------
__global__ void k_shift(const float* __restrict__ x,
                        const float* __restrict__ shift,
                        const float* __restrict__ maa_x) {
    int idx = blockIdx.x * 256 + threadIdx.x;
    if (idx >= BIGN) return;
    int c  = idx % Cc;
    int bt = idx / Cc;
    int t  = bt % Tt;
    int b  = bt / Tt;
    float xv   = x[idx];
    float prev = (t == 0) ? shift[b * Cc + c] : x[idx - Cc];
    float r    = xv + (prev - xv) * maa_x[c];
    __half h, l;
    split2h(r, h, l);
    g_pxxx[idx] = h; g_pxxx[BIGN + idx] = l;
}

// ---------------- weight fp32 -> fp16 hi -------------------------------------
__global__ void k_conv(const float* __restrict__ src,
                       __half* __restrict__ dst, int n) {
    int i = blockIdx.x * 256 + threadIdx.x;
    if (i >= n) return;
    dst[i] = __float2half_rn(src[i]);
}

// =============================================================================
// Tensor-core GEMM v6 (fp16x2: A hi/lo planes, B hi plane; fp32 accumulate):
//   4-problem batch via blockIdx.z. Tile 128x128, BK=32, 3-stage, 2 CTAs/SM.
//   Epilogue modes (per-z): 0 float, 1 tanh->float, 2 tanh->half planes,
//   3 exp(-exp(acc+bias[c]))->float, 4 float +=.
// =============================================================================
#define ASTR 40
#define BSTR 136
#define SA_H 0
#define SA_L 5120
#define SB_H 10240
#define STG  14592
#define STG_BYTES (STG*2)
#define NSTAGE 3

__device__ __forceinline__ void ldsm4(unsigned int* r, unsigned int addr) {
    asm volatile("ldmatrix.sync.aligned.m8n8.x4.shared.b16 {%0,%1,%2,%3},[%4];"
                 : "=r"(r[0]), "=r"(r[1]), "=r"(r[2]), "=r"(r[3]) : "r"(addr));
}
__device__ __forceinline__ void ldsm4t(unsigned int* r, unsigned int addr) {
    asm volatile("ldmatrix.sync.aligned.m8n8.x4.trans.shared.b16 {%0,%1,%2,%3},[%4];"
                 : "=r"(r[0]), "=r"(r[1]), "=r"(r[2]), "=r"(r[3]) : "r"(addr));
}
__device__ __forceinline__ void mma16816h(float* c, const unsigned int* a,
                                          unsigned int b0, unsigned int b1) {
    asm volatile("mma.sync.aligned.m16n8k16.row.col.f32.f16.f16.f32 "
                 "{%0,%1,%2,%3},{%4,%5,%6,%7},{%8,%9},{%0,%1,%2,%3};"
                 : "+f"(c[0]), "+f"(c[1]), "+f"(c[2]), "+f"(c[3])
                 : "r"(a[0]), "r"(a[1]), "r"(a[2]), "r"(a[3]), "r"(b0), "r"(b1));
}
__device__ __forceinline__ void cpasync16z(unsigned int daddr, const void* gp, int sz) {
    asm volatile("cp.async.ca.shared.global [%0], [%1], 16, %2;"
                 :: "r"(daddr), "l"(gp), "r"(sz));
}

__global__ __launch_bounds__(256, 2)
void k_gemm6(const __half* __restrict__ A1, const __half* __restrict__ A2,
             const __half* __restrict__ A3, const __half* __restrict__ A4,
             const __half* __restrict__ B1, const __half* __restrict__ B2,
             const __half* __restrict__ B3, const __half* __restrict__ B4,
             void* C1, void* C2, void* C3, void* C4,
             const float* __restrict__ bias,
             size_t aPlane, size_t cPlane,
             int M, int N, int K, int ldc, int4 modes) {
    const int z = blockIdx.z;
    const __half* A = (z == 0) ? A1 : (z == 1) ? A2 : (z == 2) ? A3 : A4;
    const __half* B = (z == 0) ? B1 : (z == 1) ? B2 : (z == 2) ? B3 : B4;
    void* C         = (z == 0) ? C1 : (z == 1) ? C2 : (z == 2) ? C3 : C4;
    const int mode  = (z == 0) ? modes.x : (z == 1) ? modes.y
                    : (z == 2) ? modes.z : modes.w;

    extern __shared__ __half smbuf[];
    const int tid  = threadIdx.x;
    const int lane = tid & 31;
    const int wid  = tid >> 5;
    const int wm   = wid >> 2;
    const int wn   = wid & 3;
    const int mBase = blockIdx.y * 128;
    const int nBase = blockIdx.x * 128;

    const unsigned int smB = (unsigned int)__cvta_generic_to_shared(smbuf);

    const __half* Ah = A;
    const __half* Al = A + aPlane;

    const int kChunks = K >> 5;

    auto issue = [&](int ch) {
        if (ch < kChunks) {
            const unsigned int base = smB + (unsigned int)(ch % NSTAGE) * STG_BYTES;
#pragma unroll
            for (int q2 = 0; q2 < 4; q2++) {   // A: 2 planes x 128 rows x 4 segs
                int idx = tid + 256 * q2;
                int pl  = idx >> 9;
                int rem = idx & 511;
                int row = rem >> 2;
                int seg = rem & 3;
                const __half* gp = (pl ? Al : Ah) +
                    (size_t)(mBase + row) * K + ch * 32 + seg * 8;
                unsigned int da = base +
                    (unsigned int)((pl ? SA_L : SA_H) + row * ASTR + seg * 8) * 2;
                cpasync16z(da, gp, 16);
            }
#pragma unroll
            for (int q2 = 0; q2 < 2; q2++) {   // B: 32 rows x 16 segs
                int idx = tid + 256 * q2;
                int row = idx >> 4;
                int seg = idx & 15;
                int gcol = nBase + seg * 8;
                int ok = gcol < N;
                const __half* gp = B +
                    (ok ? ((size_t)(ch * 32 + row) * N + gcol) : (size_t)0);
                unsigned int da = base +
                    (unsigned int)(SB_H + row * BSTR + seg * 8) * 2;
                cpasync16z(da, gp, ok ? 16 : 0);
            }
        }
        asm volatile("cp.async.commit_group;");
    };

    float acc[4][4][4];
#pragma unroll
    for (int i = 0; i < 4; i++)
#pragma unroll
        for (int j = 0; j < 4; j++)
#pragma unroll
            for (int q = 0; q < 4; q++) acc[i][j][q] = 0.f;

    issue(0); issue(1);

#pragma unroll 1
    for (int ch = 0; ch < kChunks; ch++) {
        asm volatile("cp.async.wait_group 1;" ::: "memory");
        __syncthreads();
        issue(ch + 2);

        const unsigned int sb = smB + (unsigned int)(ch % NSTAGE) * STG_BYTES;
#pragma unroll
        for (int ks = 0; ks < 2; ks++) {
            const int k0 = ks * 16;
            unsigned int ah[4][4], al[4][4], bh[2][4];
#pragma unroll
            for (int mf = 0; mf < 4; mf++) {
                int row = wm * 64 + mf * 16 + (lane & 15);
                int col = k0 + (lane >> 4) * 8;
                unsigned int ad = sb + (unsigned int)(row * ASTR + col) * 2;
                ldsm4(ah[mf], ad + SA_H * 2);
                ldsm4(al[mf], ad + SA_L * 2);
            }
#pragma unroll
            for (int nf2 = 0; nf2 < 2; nf2++) {
                int rowk = k0 + (lane & 15);
                int coln = wn * 32 + nf2 * 16 + (lane >> 4) * 8;
                unsigned int bd = sb + (unsigned int)(rowk * BSTR + coln) * 2;
                ldsm4t(bh[nf2], bd + SB_H * 2);
            }
#pragma unroll
            for (int mf = 0; mf < 4; mf++) {
#pragma unroll
                for (int nf = 0; nf < 4; nf++) {
                    unsigned int b0 = bh[nf >> 1][(nf & 1) * 2];
                    unsigned int b1 = bh[nf >> 1][(nf & 1) * 2 + 1];
                    mma16816h(acc[mf][nf], ah[mf], b0, b1);
                    mma16816h(acc[mf][nf], al[mf], b0, b1);
                }
            }
        }
    }

    // epilogue
#pragma unroll
    for (int mf = 0; mf < 4; mf++) {
#pragma unroll
        for (int nf = 0; nf < 4; nf++) {
            int r = mBase + wm * 64 + mf * 16 + (lane >> 2);
            int c = nBase + wn * 32 + nf * 8 + (lane & 3) * 2;
            if (c < N) {
                float a0 = acc[mf][nf][0], a1 = acc[mf][nf][1];
                float a2 = acc[mf][nf][2], a3 = acc[mf][nf][3];
                size_t i0 = (size_t)r * ldc + c;
                size_t i1 = (size_t)(r + 8) * ldc + c;
                if (mode == 0) {
                    float* Cf = (float*)C;
                    *(float2*)&Cf[i0] = make_float2(a0, a1);
                    *(float2*)&Cf[i1] = make_float2(a2, a3);
                } else if (mode == 1) {
                    float* Cf = (float*)C;
                    *(float2*)&Cf[i0] = make_float2(tanhf(a0), tanhf(a1));
                    *(float2*)&Cf[i1] = make_float2(tanhf(a2), tanhf(a3));
                } else if (mode == 2) {
                    __half* Chp = (__half*)C;
                    a0 = tanhf(a0); a1 = tanhf(a1);
                    a2 = tanhf(a2); a3 = tanhf(a3);
                    __half h0,l0,h1,l1,h2,l2,h3,l3;
                    split2h(a0,h0,l0); split2h(a1,h1,l1);
                    split2h(a2,h2,l2); split2h(a3,h3,l3);
                    *(__half2*)&Chp[i0] = __halves2half2(h0, h1);
                    *(__half2*)&Chp[i1] = __halves2half2(h2, h3);
                    *(__half2*)&Chp[cPlane + i0] = __halves2half2(l0, l1);
                    *(__half2*)&Chp[cPlane + i1] = __halves2half2(l2, l3);
                } else if (mode == 3) {
                    float b0 = bias[c], b1 = bias[c + 1];
                    float* Cf = (float*)C;
                    *(float2*)&Cf[i0] =
                        make_float2(expf(-expf(a0 + b0)), expf(-expf(a1 + b1)));
                    *(float2*)&Cf[i1] =
                        make_float2(expf(-expf(a2 + b0)), expf(-expf(a3 + b1)));
                } else {   // 4: accumulate
                    float* Cf = (float*)C;
                    Cf[i0] += a0; Cf[i0 + 1] += a1;
                    Cf[i1] += a2; Cf[i1 + 1] += a3;
                }
            }
        }
    }
}

// ---------------- E2: 5-way LoRA mix -> fp16 planes -------------------------
__global__ __launch_bounds__(256, 3)
void k_mix(const float* __restrict__ x,
           const float* __restrict__ shift,
           const float* __restrict__ w2,
           const float* __restrict__ mr, const float* __restrict__ mk,
           const float* __restrict__ mv, const float* __restrict__ mw,
           const float* __restrict__ mv2) {
    __shared__ float hs[32][160];
    __shared__ float ws[160][32];
    int rowBase = blockIdx.x * 32;
    int colBase = blockIdx.y * 32;
    int tid = threadIdx.x;

    for (int l = tid; l < 32 * 160; l += 256) {
        int rr = l / 160, d = l % 160;
        hs[rr][d] = g_hpre[(rowBase + rr) * 160 + d];
    }
    for (int l = tid; l < 160 * 32; l += 256) {
        int fd = l / 32, cc = l % 32;
        ws[fd][cc] = w2[fd * Cc + colBase + cc];
    }
    __syncthreads();

    int cc = tid % 32;
    int r0 = tid / 32;
    int c  = colBase + cc;
    float tr = mr[c], tk = mk[c], tv = mv[c], tw = mw[c], tv2 = mv2[c];

    for (int rr = r0; rr < 32; rr += 8) {
        float m0 = 0, m1 = 0, m2 = 0, m3 = 0, m4 = 0;
#pragma unroll 8
        for (int d = 0; d < 32; d++) {
            m0 = fmaf(hs[rr][d],       ws[d][cc],       m0);
            m1 = fmaf(hs[rr][32 + d],  ws[32 + d][cc],  m1);
            m2 = fmaf(hs[rr][64 + d],  ws[64 + d][cc],  m2);
            m3 = fmaf(hs[rr][96 + d],  ws[96 + d][cc],  m3);
            m4 = fmaf(hs[rr][128 + d], ws[128 + d][cc], m4);
        }
        int bt  = rowBase + rr;
        int t   = bt % Tt;
        int b   = bt / Tt;
        int idx = bt * Cc + c;
        float xval = x[idx];
        float prev = (t == 0) ? shift[b * Cc + c] : x[idx - Cc];
        float dx   = prev - xval;
        float vr  = xval + dx * (tr  + m0);
        float vk  = xval + dx * (tk  + m1);
        float vv  = xval + dx * (tv  + m2);
        float vw  = xval + dx * (tw  + m3);
        float vv2 = xval + dx * (tv2 + m4);
        __half h, l;
        split2h(vr,  h, l); g_pxr [idx] = h; g_pxr [BIGN + idx] = l;
        split2h(vk,  h, l); g_pxk [idx] = h; g_pxk [BIGN + idx] = l;
        split2h(vv,  h, l); g_pxv [idx] = h; g_pxv [BIGN + idx] = l;
        split2h(vw,  h, l); g_pxw [idx] = h; g_pxw [BIGN + idx] = l;
        split2h(vv2, h, l); g_pxv2[idx] = h; g_pxv2[BIGN + idx] = l;
    }
}

// ---------------- S: WKV scan, 256 threads, 4 lanes/column ------------------
#define CHUNK 8
__device__ __forceinline__ void cpasync16(unsigned int daddr, const void* gp) {
    asm volatile("cp.async.ca.shared.global [%0], [%1], 16;"
                 :: "r"(daddr), "l"(gp));
}
__global__ __launch_bounds__(256)
void k_scan(const float* __restrict__ wkv_in,
            float* __restrict__ wkv_out) {
    const int h = blockIdx.x, b = blockIdx.y;
    const int tid  = threadIdx.x;
    const int lane = tid & 31;
    const int wid  = tid >> 5;
    const int jj   = wid * 8 + (lane >> 2);
    const int q    = lane & 3;

    __shared__ float sbuf[2][4][CHUNK][64];
    const unsigned int sb = (unsigned int)__cvta_generic_to_shared(&sbuf[0][0][0][0]);

    float state[16];
#pragma unroll
    for (int i = 0; i < 16; i++)
        state[i] = wkv_in[(size_t)((b * Hh + h) * Nn + q * 16 + i) * Nn + jj];

    const float* srcs[4] = { g_r, g_k, g_decay, g_v };
    const size_t rowOff = (size_t)h * Nn;

    auto issue = [&](int buf, int t0) {
#pragma unroll
        for (int p = 0; p < 2; p++) {
            int l   = tid + 256 * p;
            int arr = l >> 7;
            int rem = l & 127;
            int t   = rem >> 4;
            int seg = rem & 15;
            const float* gp = srcs[arr] +
                (size_t)(b * Tt + t0 + t) * Cc + rowOff + seg * 4;
            unsigned int da = sb +
                (unsigned int)((((buf * 4 + arr) * CHUNK + t) * 64) + seg * 4) * 4;
            cpasync16(da, gp);
        }
        asm volatile("cp.async.commit_group;");
    };

    issue(0, 0);
    asm volatile("cp.async.wait_group 0;" ::: "memory");
    __syncthreads();

    const int nch = Tt / CHUNK;
    for (int ch = 0; ch < nch; ch++) {
        const int cur = ch & 1;
        if (ch + 1 < nch) issue(cur ^ 1, (ch + 1) * CHUNK);

        const int t0 = ch * CHUNK;
#pragma unroll
        for (int tt = 0; tt < CHUNK; tt++) {
            const float4* rs4 = (const float4*)&sbuf[cur][0][tt][q * 16];
            const float4* ks4 = (const float4*)&sbuf[cur][1][tt][q * 16];
            const float4* ds4 = (const float4*)&sbuf[cur][2][tt][q * 16];
            const float vj = sbuf[cur][3][tt][jj];

            float y = 0.f;
#pragma unroll
            for (int i4 = 0; i4 < 4; i4++) {
                float4 r4 = rs4[i4], k4 = ks4[i4], d4 = ds4[i4];
                float kx, kv;
                float s0 = state[4*i4+0], s1 = state[4*i4+1];
                float s2 = state[4*i4+2], s3 = state[4*i4+3];
                y = fmaf(r4.x, s0, y);
                kx = fmaf(-k4.x, d4.x, k4.x); kv = kx * vj;
                state[4*i4+0] = fmaf(s0, d4.x, kv);
                y = fmaf(r4.y, s1, y);
                kx = fmaf(-k4.y, d4.y, k4.y); kv = kx * vj;
                state[4*i4+1] = fmaf(s1, d4.y, kv);
                y = fmaf(r4.z, s2, y);
                kx = fmaf(-k4.z, d4.z, k4.z); kv = kx * vj;
                state[4*i4+2] = fmaf(s2, d4.z, kv);
                y = fmaf(r4.w, s3, y);
                kx = fmaf(-k4.w, d4.w, k4.w); kv = kx * vj;
                state[4*i4+3] = fmaf(s3, d4.w, kv);
            }
            y += __shfl_xor_sync(0xffffffffu, y, 1);
            y += __shfl_xor_sync(0xffffffffu, y, 2);
            if (q == 0)
                g_ys[(size_t)(b * Tt + t0 + tt) * Cc + rowOff + jj] = y;
        }

        asm volatile("cp.async.wait_group 0;" ::: "memory");
        __syncthreads();
    }

#pragma unroll
    for (int i = 0; i < 16; i++)
        wkv_out[(size_t)((b * Hh + h) * Nn + q * 16 + i) * Nn + jj] = state[i];
}

// ---------------- E5: y = LN(ys + v2) -> fp16 planes -------------------------
__global__ void k_ln(const float* __restrict__ lnw,
                     const float* __restrict__ lnb) {
    int row = blockIdx.x;
    int tid = threadIdx.x;
    const float* a  = g_ys + (size_t)row * Cc;
    const float* bp = g_v2 + (size_t)row * Cc;
    float s = 0.f, ss = 0.f;
    for (int c = tid; c < Cc; c += 256) {
        float v = a[c] + bp[c];
        s += v; ss += v * v;
    }
    __shared__ float sh1[256], sh2[256];
    sh1[tid] = s; sh2[tid] = ss;
    __syncthreads();
    for (int st = 128; st > 0; st >>= 1) {
        if (tid < st) { sh1[tid] += sh1[tid + st]; sh2[tid] += sh2[tid + st]; }
        __syncthreads();
    }
    float mu  = sh1[0] / Cc;
    float var = sh2[0] / Cc - mu * mu;
    float rstd = rsqrtf(var + 1e-5f);
    for (int c = tid; c < Cc; c += 256) {
        float v = a[c] + bp[c];
        float res = (v - mu) * rstd * lnw[c] + lnb[c];
        __half h, l;
        split2h(res, h, l);
        size_t idx = (size_t)row * Cc + c;
        g_pyn[idx] = h; g_pyn[BIGN + idx] = l;
    }
}

// ---------------- E6: shift_state_out ---------------------------------------
__global__ void k_copyshift(const float* __restrict__ x, float* __restrict__ out) {
    int i = blockIdx.x * 256 + threadIdx.x;
    if (i >= Bb * Cc) return;
    int b = i / Cc, c = i % Cc;
    out[i] = x[(size_t)(b * Tt + Tt - 1) * Cc + c];
}

// ---------------- launcher ---------------------------------------------------
extern "C" void kernel_launch(void* const* d_in, const int* in_sizes, int n_in,
                              void* d_out, int out_size) {
    const float* x        = (const float*)d_in[0];
    const float* shift_in = (const float*)d_in[1];
    const float* wkv_in   = (const float*)d_in[2];
    const float* maa_x    = (const float*)d_in[3];
    const float* maa_r    = (const float*)d_in[4];
    const float* maa_k    = (const float*)d_in[5];
    const float* maa_v    = (const float*)d_in[6];
    const float* maa_w    = (const float*)d_in[7];
    const float* maa_v2   = (const float*)d_in[8];
    const float* maa_w1   = (const float*)d_in[9];
    const float* maa_w2   = (const float*)d_in[10];
    const float* tdecay   = (const float*)d_in[11];
    const float* dec_w1   = (const float*)d_in[12];
    const float* dec_w2   = (const float*)d_in[13];
    const float* v2_w1    = (const float*)d_in[14];
    const float* v2_w2    = (const float*)d_in[15];
    const float* W_r      = (const float*)d_in[16];
    const float* W_k      = (const float*)d_in[17];
    const float* W_v      = (const float*)d_in[18];
    const float* W_o      = (const float*)d_in[19];
    const float* ln_w     = (const float*)d_in[20];
    const float* ln_b     = (const float*)d_in[21];

    float* out_y     = (float*)d_out;
    float* out_shift = out_y + (size_t)BT * Cc;
    float* out_wkv   = out_shift + (size_t)Bb * Cc;

    float *rb = 0, *kb = 0, *vb = 0, *v2b = 0, *decay = 0, *hpre = 0;
    __half *pxxx = 0, *pxr = 0, *pxk = 0, *pxv = 0, *pxw = 0, *pxv2 = 0, *pyn = 0;
    __half *ptw = 0, *ptv = 0;
    __half *pWr = 0, *pWk = 0, *pWv = 0, *pWo = 0;
    __half *pW1 = 0, *pWd = 0, *pWe = 0, *pWd2 = 0, *pWe2 = 0;
    cudaGetSymbolAddress((void**)&rb,    g_r);
    cudaGetSymbolAddress((void**)&kb,    g_k);
    cudaGetSymbolAddress((void**)&vb,    g_v);
    cudaGetSymbolAddress((void**)&v2b,   g_v2);
    cudaGetSymbolAddress((void**)&decay, g_decay);
    cudaGetSymbolAddress((void**)&hpre,  g_hpre);
    cudaGetSymbolAddress((void**)&pxxx,  g_pxxx);
    cudaGetSymbolAddress((void**)&pxr,   g_pxr);
    cudaGetSymbolAddress((void**)&pxk,   g_pxk);
    cudaGetSymbolAddress((void**)&pxv,   g_pxv);
    cudaGetSymbolAddress((void**)&pxw,   g_pxw);
    cudaGetSymbolAddress((void**)&pxv2,  g_pxv2);
    cudaGetSymbolAddress((void**)&pyn,   g_pyn);
    cudaGetSymbolAddress((void**)&ptw,   g_ptw);
    cudaGetSymbolAddress((void**)&ptv,   g_ptv);
    cudaGetSymbolAddress((void**)&pWr,   g_pWr);
    cudaGetSymbolAddress((void**)&pWk,   g_pWk);
    cudaGetSymbolAddress((void**)&pWv,   g_pWv);
    cudaGetSymbolAddress((void**)&pWo,   g_pWo);
    cudaGetSymbolAddress((void**)&pW1,   g_pW1);
    cudaGetSymbolAddress((void**)&pWd,   g_pWd);
    cudaGetSymbolAddress((void**)&pWe,   g_pWe);
    cudaGetSymbolAddress((void**)&pWd2,  g_pWd2);
    cudaGetSymbolAddress((void**)&pWe2,  g_pWe2);

    cudaFuncSetAttribute(k_gemm6,
                         cudaFuncAttributeMaxDynamicSharedMemorySize,
                         NSTAGE * STG_BYTES);
    const int gemmSmem = NSTAGE * STG_BYTES;

    // weight conversions (fp16 hi only)
    k_conv<<<WN / 256, 256>>>(W_r, pWr, WN);
    k_conv<<<WN / 256, 256>>>(W_k, pWk, WN);
    k_conv<<<WN / 256, 256>>>(W_v, pWv, WN);
    k_conv<<<WN / 256, 256>>>(W_o, pWo, WN);
    k_conv<<<(Cc * 160) / 256, 256>>>(maa_w1, pW1, Cc * 160);
    k_conv<<<(Cc * 64) / 256, 256>>>(dec_w1, pWd, Cc * 64);
    k_conv<<<(Cc * 64) / 256, 256>>>(v2_w1, pWe, Cc * 64);
    k_conv<<<(Cc * 64) / 256, 256>>>(dec_w2, pWd2, Cc * 64);
    k_conv<<<(Cc * 64) / 256, 256>>>(v2_w2, pWe2, Cc * 64);

    // E1: token shift -> xxx planes
    k_shift<<<BIGN / 256, 256>>>(x, shift_in, maa_x);

    // G1: hpre = tanh(xxx @ maa_w1) [8192,160] (mode 1)
    k_gemm6<<<dim3(2, BT / 128, 1), 256, gemmSmem>>>(
        pxxx, pxxx, pxxx, pxxx, pW1, pW1, pW1, pW1,
        hpre, hpre, hpre, hpre, tdecay,
        (size_t)BIGN, 0, BT, 160, Cc, 160, make_int4(1, 1, 1, 1));

    // E2: 5-way mix -> planes
    k_mix<<<dim3(BT / 32, Cc / 32), 256>>>(x, shift_in, maa_w2,
                                           maa_r, maa_k, maa_v, maa_w, maa_v2);

    // Projections batched (z=4, mode 0)
    k_gemm6<<<dim3(16, BT / 128, 4), 256, gemmSmem>>>(
        pxr, pxk, pxv, pxv2, pWr, pWk, pWv, pWv,
        rb, kb, vb, v2b, tdecay,
        (size_t)BIGN, 0, BT, Cc, Cc, Cc, make_int4(0, 0, 0, 0));

    // LoRA GEMMs (z=2, mode 2: tanh -> half planes)
    k_gemm6<<<dim3(1, BT / 128, 2), 256, gemmSmem>>>(
        pxw, pxv2, pxv2, pxv2, pWd, pWe, pWe, pWe,
        ptw, ptv, ptv, ptv, tdecay,
        (size_t)BIGN, (size_t)BT * 64, BT, 64, Cc, 64, make_int4(2, 2, 2, 2));

    // Epilogue GEMMs (z=2): decay (mode 3) and v2 += (mode 4), K=64
    k_gemm6<<<dim3(16, BT / 128, 2), 256, gemmSmem>>>(
        ptw, ptv, ptv, ptv, pWd2, pWe2, pWe2, pWe2,
        decay, v2b, v2b, v2b, tdecay,
        (size_t)BT * 64, 0, BT, Cc, 64, Cc, make_int4(3, 4, 4, 4));

    // WKV scan (k * (1-decay) fused)
    k_scan<<<dim3(Hh, Bb), 256>>>(wkv_in, out_wkv);

    // LayerNorm(ys + v2) -> planes
    k_ln<<<BT, 256>>>(ln_w, ln_b);

    // Output GEMM: y = ynorm @ W_o (mode 0)
    k_gemm6<<<dim3(16, BT / 128, 1), 256, gemmSmem>>>(
        pyn, pyn, pyn, pyn, pWo, pWo, pWo, pWo,
        out_y, out_y, out_y, out_y, tdecay,
        (size_t)BIGN, 0, BT, Cc, Cc, Cc, make_int4(0, 0, 0, 0));

    // shift state out
    k_copyshift<<<(Bb * Cc + 255) / 256, 256>>>(x, out_shift);
}